// round 2
// baseline (speedup 1.0000x reference)
#include <cuda_runtime.h>
#include <cstdint>

#define NN      50000
#define NGRAPH  64
#define HID     128
#define NLAYERS 4

// ---------------- scratch (no allocations allowed) ----------------
__device__ float g_t[NN * HID];     // h @ W  (messages source)
__device__ float g_act[NN * HID];   // activation / aggregation buffer
__device__ float g_deg[NN];
__device__ float g_dinv[NN];
__device__ float g_pooled[NGRAPH * HID];
__device__ int   g_idx64;           // 1 if index buffers are int64, 0 if int32

// ---------------- dtype detection (warp-parallel) ----------------
// little-endian int64 with small values => odd 32-bit words are all zero.
__global__ void detect_dtype_kernel(const int* __restrict__ e) {
    int lane = threadIdx.x;
    int nz = 0;
    // check 64 odd words (= hi halves of first 64 int64 elements)
    if (e[1 + 2 * lane] != 0) nz = 1;
    if (e[1 + 2 * (lane + 32)] != 0) nz = 1;
    unsigned m = __ballot_sync(0xFFFFFFFFu, nz);
    if (lane == 0) g_idx64 = (m == 0u) ? 1 : 0;
}

__device__ __forceinline__ int load_index(const void* p, long long i, int is64) {
    if (is64) return (int)(((const long long*)p)[i]);
    return ((const int*)p)[i];
}

// ---------------- degree / norm ----------------------------------
__global__ void deg_init_kernel(int n) {
    int i = blockIdx.x * blockDim.x + threadIdx.x;
    if (i < n) g_deg[i] = 1.0f;   // self-loop
}

__global__ void deg_accum_kernel(const void* __restrict__ eidx, int E) {
    int is64 = g_idx64;
    int i = blockIdx.x * blockDim.x + threadIdx.x;
    if (i < E) {
        int c = load_index(eidx, (long long)E + i, is64);  // target/col
        atomicAdd(&g_deg[c], 1.0f);
    }
}

__global__ void dinv_kernel(int n) {
    int i = blockIdx.x * blockDim.x + threadIdx.x;
    if (i < n) g_dinv[i] = rsqrtf(g_deg[i]);   // deg >= 1 always
}

// ---------------- fused GEMM -------------------------------------
// C[M,128] = op(A)[M,128] @ W[128,128]
//   PRO:  op(a)[r][c] = relu(a[r][c] + pro_bias[c])   (pro_bias may be null)
//   SELF: also writes act[r][:] = C[r][:] * dinv[r]^2 (self-loop message)
//         and t[r][:] = C[r][:]
//   !SELF: writes outC[r][:] = C[r][:] + epi_bias[c]
// BM=128, BN=128, BK=32; 256 threads, 8x8 per thread.
template<bool PRO, bool SELF>
__global__ __launch_bounds__(256) void gemm_kernel(
    const float* A, const float* __restrict__ W,
    const float* __restrict__ pro_bias, const float* __restrict__ epi_bias,
    float* outC, float* outAct, int M)
{
    __shared__ float As[128 * 32];
    __shared__ float Bs[32 * 128];

    const int tid = threadIdx.x;
    const int ty = tid >> 4;        // 0..15
    const int tx = tid & 15;        // 0..15
    const int row0 = blockIdx.x * 128;

    float acc[8][8];
#pragma unroll
    for (int i = 0; i < 8; i++)
#pragma unroll
        for (int j = 0; j < 8; j++) acc[i][j] = 0.0f;

    for (int kc = 0; kc < 128; kc += 32) {
        // load A tile: 128x32 floats = 1024 float4, 4 per thread
#pragma unroll
        for (int l = 0; l < 4; l++) {
            int f = tid + l * 256;          // 0..1023
            int r = f >> 3;                 // row in tile
            int c4 = f & 7;                 // float4 column
            int grow = row0 + r;
            float4 v = make_float4(0.f, 0.f, 0.f, 0.f);
            if (grow < M) {
                v = *(const float4*)&A[(size_t)grow * 128 + kc + c4 * 4];
                if (PRO) {
                    float4 b = make_float4(0.f, 0.f, 0.f, 0.f);
                    if (pro_bias) b = ((const float4*)pro_bias)[(kc >> 2) + c4];
                    v.x = fmaxf(v.x + b.x, 0.0f);
                    v.y = fmaxf(v.y + b.y, 0.0f);
                    v.z = fmaxf(v.z + b.z, 0.0f);
                    v.w = fmaxf(v.w + b.w, 0.0f);
                }
            }
            *(float4*)&As[r * 32 + c4 * 4] = v;
        }
        // load B tile: 32x128 floats = 1024 float4, 4 per thread
#pragma unroll
        for (int l = 0; l < 4; l++) {
            int f = tid + l * 256;
            int r = f >> 5;                 // 0..31
            int c4 = f & 31;
            *(float4*)&Bs[r * 128 + c4 * 4] =
                *(const float4*)&W[(size_t)(kc + r) * 128 + c4 * 4];
        }
        __syncthreads();

#pragma unroll
        for (int k = 0; k < 32; k++) {
            float a[8], b[8];
#pragma unroll
            for (int i = 0; i < 8; i++) a[i] = As[(ty * 8 + i) * 32 + k];
            *(float4*)&b[0] = *(float4*)&Bs[k * 128 + tx * 8];
            *(float4*)&b[4] = *(float4*)&Bs[k * 128 + tx * 8 + 4];
#pragma unroll
            for (int i = 0; i < 8; i++)
#pragma unroll
                for (int j = 0; j < 8; j++)
                    acc[i][j] = fmaf(a[i], b[j], acc[i][j]);
        }
        __syncthreads();
    }

    // epilogue
    float bv[8];
#pragma unroll
    for (int j = 0; j < 8; j++)
        bv[j] = (!SELF && epi_bias) ? epi_bias[tx * 8 + j] : 0.0f;

#pragma unroll
    for (int i = 0; i < 8; i++) {
        int grow = row0 + ty * 8 + i;
        if (grow < M) {
            if (SELF) {
                float d = g_dinv[grow];
                float s = d * d;
                float r[8], ra[8];
#pragma unroll
                for (int j = 0; j < 8; j++) { r[j] = acc[i][j]; ra[j] = acc[i][j] * s; }
                *(float4*)&outC[(size_t)grow * 128 + tx * 8]     = *(float4*)&r[0];
                *(float4*)&outC[(size_t)grow * 128 + tx * 8 + 4] = *(float4*)&r[4];
                *(float4*)&outAct[(size_t)grow * 128 + tx * 8]     = *(float4*)&ra[0];
                *(float4*)&outAct[(size_t)grow * 128 + tx * 8 + 4] = *(float4*)&ra[4];
            } else {
                float r[8];
#pragma unroll
                for (int j = 0; j < 8; j++) r[j] = acc[i][j] + bv[j];
                *(float4*)&outC[(size_t)grow * 128 + tx * 8]     = *(float4*)&r[0];
                *(float4*)&outC[(size_t)grow * 128 + tx * 8 + 4] = *(float4*)&r[4];
            }
        }
    }
}

// ---------------- edge scatter: one warp per edge ------------------------
__global__ __launch_bounds__(256) void scatter_kernel(const void* __restrict__ eidx, int E) {
    const int is64 = g_idx64;
    const int lane = threadIdx.x & 31;
    int w = (blockIdx.x * blockDim.x + threadIdx.x) >> 5;
    const int nw = (gridDim.x * blockDim.x) >> 5;

    for (int e = w; e < E; e += nw) {
        int s, t;
        if (is64) {
            s = (int)((const long long*)eidx)[e];
            t = (int)((const long long*)eidx)[(long long)E + e];
        } else {
            s = ((const int*)eidx)[e];
            t = ((const int*)eidx)[E + e];
        }
        float nrm = g_dinv[s] * g_dinv[t];
        float4 v = ((const float4*)(g_t + (size_t)s * HID))[lane];
        float* dst = g_act + (size_t)t * HID + lane * 4;
        asm volatile(
            "red.global.add.v4.f32 [%0], {%1, %2, %3, %4};"
            :: "l"(dst), "f"(v.x * nrm), "f"(v.y * nrm),
               "f"(v.z * nrm), "f"(v.w * nrm)
            : "memory");
    }
}

// ---------------- mean pool per graph (batch sorted), fused bias+relu ----
__device__ __forceinline__ int lower_bound_batch(const void* batch, int n, int val, int is64) {
    int lo = 0, hi = n;
    while (lo < hi) {
        int mid = (lo + hi) >> 1;
        long long b = is64 ? ((const long long*)batch)[mid]
                           : (long long)((const int*)batch)[mid];
        if (b < val) lo = mid + 1; else hi = mid;
    }
    return lo;
}

__global__ void pool_kernel(const void* __restrict__ batch,
                            const float* __restrict__ bias, int n) {
    const int g = blockIdx.x;
    const int tid = threadIdx.x;
    __shared__ int slo, shi;
    if (tid == 0) {
        int is64 = g_idx64;
        slo = lower_bound_batch(batch, n, g, is64);
        shi = lower_bound_batch(batch, n, g + 1, is64);
    }
    __syncthreads();
    const float b = bias[tid];
    float s0 = 0.f, s1 = 0.f, s2 = 0.f, s3 = 0.f;
    int lo = slo, hi = shi;
    int r = lo;
    for (; r + 4 <= hi; r += 4) {
        s0 += fmaxf(g_act[(size_t)(r + 0) * HID + tid] + b, 0.0f);
        s1 += fmaxf(g_act[(size_t)(r + 1) * HID + tid] + b, 0.0f);
        s2 += fmaxf(g_act[(size_t)(r + 2) * HID + tid] + b, 0.0f);
        s3 += fmaxf(g_act[(size_t)(r + 3) * HID + tid] + b, 0.0f);
    }
    for (; r < hi; r++)
        s0 += fmaxf(g_act[(size_t)r * HID + tid] + b, 0.0f);
    float sum = (s0 + s1) + (s2 + s3);
    float cnt = (float)(hi - lo);
    g_pooled[g * HID + tid] = sum / fmaxf(cnt, 1.0f);
}

// ---------------- heads: out[head][g][:] = pooled[g] @ W_head + b_head ---
__global__ void heads_kernel(
    const float* __restrict__ Wd, const float* __restrict__ bd,
    const float* __restrict__ Ws, const float* __restrict__ bsn,
    const float* __restrict__ Wr, const float* __restrict__ br,
    float* __restrict__ out)
{
    const int g = blockIdx.x;
    const int head = blockIdx.y;
    const int j = threadIdx.x;
    __shared__ float p[HID];
    p[j] = g_pooled[g * HID + j];
    __syncthreads();

    const float* W = (head == 0) ? Wd : (head == 1) ? Ws : Wr;
    const float* b = (head == 0) ? bd : (head == 1) ? bsn : br;
    float s = b[j];
#pragma unroll 8
    for (int k = 0; k < HID; k++)
        s = fmaf(p[k], W[k * HID + j], s);
    out[(size_t)head * NGRAPH * HID + g * HID + j] = s;
}

// ---------------- launch --------------------------------------------------
extern "C" void kernel_launch(void* const* d_in, const int* in_sizes, int n_in,
                              void* d_out, int out_size)
{
    const float* x      = (const float*)d_in[0];
    const void*  eidx   = d_in[1];
    const void*  batch  = d_in[2];
    const float* W_in   = (const float*)d_in[3];
    const float* b_in   = (const float*)d_in[4];
    const float* conv_W = (const float*)d_in[5];
    const float* conv_b = (const float*)d_in[6];
    const float* W_def  = (const float*)d_in[7];
    const float* b_def  = (const float*)d_in[8];
    const float* W_syn  = (const float*)d_in[9];
    const float* b_syn  = (const float*)d_in[10];
    const float* W_rel  = (const float*)d_in[11];
    const float* b_rel  = (const float*)d_in[12];
    float* out = (float*)d_out;

    const int N = in_sizes[0] / HID;       // 50000
    const int E = in_sizes[1] / 2;         // 640000

    void *pt, *pa;
    cudaGetSymbolAddress(&pt, g_t);
    cudaGetSymbolAddress(&pa, g_act);
    float* t_buf   = (float*)pt;
    float* act_buf = (float*)pa;

    const int T = 256;
    const int GB = (N + 127) / 128;

    // 0. index dtype detection
    detect_dtype_kernel<<<1, 32>>>((const int*)eidx);

    // 1. gcn_norm: degrees + dinv
    deg_init_kernel<<<(N + T - 1) / T, T>>>(N);
    deg_accum_kernel<<<(E + T - 1) / T, T>>>(eidx, E);
    dinv_kernel<<<(N + T - 1) / T, T>>>(N);

    // 2. input layer: act = x @ W_in + b_in   (pre-activation; relu fused into
    //    the next GEMM's prologue)
    gemm_kernel<false, false><<<GB, 256>>>(x, W_in, nullptr, b_in,
                                           act_buf, nullptr, N);

    // 3. GCN layers: per layer exactly 2 kernels
    for (int l = 0; l < NLAYERS; l++) {
        const float* pro_b = (l == 0) ? nullptr : conv_b + (size_t)(l - 1) * HID;
        // t = relu(act + pro_b) @ W_l ;  act = t * dinv^2  (self-loop message)
        gemm_kernel<true, true><<<GB, 256>>>(
            act_buf, conv_W + (size_t)l * HID * HID, pro_b, nullptr,
            t_buf, act_buf, N);
        // act += sum_{edges} norm * t[src]
        scatter_kernel<<<4096, 256>>>(eidx, E);
    }

    // 4. global mean pool with fused final bias+relu
    pool_kernel<<<NGRAPH, HID>>>(batch, conv_b + (size_t)(NLAYERS - 1) * HID, N);

    // 5. output heads
    heads_kernel<<<dim3(NGRAPH, 3), HID>>>(W_def, b_def, W_syn, b_syn,
                                           W_rel, b_rel, out);
}

// round 3
// speedup vs baseline: 1.4147x; 1.4147x over previous
#include <cuda_runtime.h>
#include <cstdint>

#define NN      50000
#define NGRAPH  64
#define HID     128
#define NLAYERS 4
#define CAP     192     // per-node in-edge capacity (max in-degree ~45 expected)

// ---------------- scratch (no allocations allowed) ----------------
__device__ float g_t[NN * HID];       // h @ W  (message source)
__device__ float g_act[NN * HID];     // activation / aggregation buffer
__device__ int   g_srcs[NN * CAP];    // bucketed in-edge source lists
__device__ int   g_cursor[NN];        // in-degree (w/o self loop)
__device__ float g_pooled[NGRAPH * HID];
__device__ int   g_idx64;             // 1 if index buffers are int64

// ---------------- dtype detection (warp-parallel) ----------------
__global__ void detect_dtype_kernel(const int* __restrict__ e) {
    int lane = threadIdx.x;
    int nz = 0;
    if (e[1 + 2 * lane] != 0) nz = 1;
    if (e[1 + 2 * (lane + 32)] != 0) nz = 1;
    unsigned m = __ballot_sync(0xFFFFFFFFu, nz);
    if (lane == 0) g_idx64 = (m == 0u) ? 1 : 0;
}

// ---------------- adjacency build --------------------------------
__global__ void zero_kernel(int n) {
    int i = blockIdx.x * blockDim.x + threadIdx.x;
    if (i < n) g_cursor[i] = 0;
}

__global__ void fill_kernel(const void* __restrict__ eidx, int E) {
    const int is64 = g_idx64;
    int i = blockIdx.x * blockDim.x + threadIdx.x;
    if (i < E) {
        int s, t;
        if (is64) {
            s = (int)((const long long*)eidx)[i];
            t = (int)((const long long*)eidx)[(long long)E + i];
        } else {
            s = ((const int*)eidx)[i];
            t = ((const int*)eidx)[E + i];
        }
        int p = atomicAdd(&g_cursor[t], 1);
        if (p < CAP) g_srcs[t * CAP + p] = s;
    }
}

// ---------------- fused GEMM -------------------------------------
// C[M,128] = op(A)[M,128] @ W[128,128] (+ epi_bias)
//   PRO: op(a)[r][c] = relu(a[r][c] + pro_bias[c])   (pro_bias may be null)
// BM=128, BN=128, BK=32; 256 threads, 8x8 per thread.
template<bool PRO>
__global__ __launch_bounds__(256) void gemm_kernel(
    const float* A, const float* __restrict__ W,
    const float* __restrict__ pro_bias, const float* __restrict__ epi_bias,
    float* outC, int M)
{
    __shared__ float As[128 * 32];
    __shared__ float Bs[32 * 128];

    const int tid = threadIdx.x;
    const int ty = tid >> 4;
    const int tx = tid & 15;
    const int row0 = blockIdx.x * 128;

    float acc[8][8];
#pragma unroll
    for (int i = 0; i < 8; i++)
#pragma unroll
        for (int j = 0; j < 8; j++) acc[i][j] = 0.0f;

    for (int kc = 0; kc < 128; kc += 32) {
#pragma unroll
        for (int l = 0; l < 4; l++) {
            int f = tid + l * 256;
            int r = f >> 3;
            int c4 = f & 7;
            int grow = row0 + r;
            float4 v = make_float4(0.f, 0.f, 0.f, 0.f);
            if (grow < M) {
                v = *(const float4*)&A[(size_t)grow * 128 + kc + c4 * 4];
                if (PRO) {
                    float4 b = make_float4(0.f, 0.f, 0.f, 0.f);
                    if (pro_bias) b = ((const float4*)pro_bias)[(kc >> 2) + c4];
                    v.x = fmaxf(v.x + b.x, 0.0f);
                    v.y = fmaxf(v.y + b.y, 0.0f);
                    v.z = fmaxf(v.z + b.z, 0.0f);
                    v.w = fmaxf(v.w + b.w, 0.0f);
                }
            }
            *(float4*)&As[r * 32 + c4 * 4] = v;
        }
#pragma unroll
        for (int l = 0; l < 4; l++) {
            int f = tid + l * 256;
            int r = f >> 5;
            int c4 = f & 31;
            *(float4*)&Bs[r * 128 + c4 * 4] =
                *(const float4*)&W[(size_t)(kc + r) * 128 + c4 * 4];
        }
        __syncthreads();

#pragma unroll
        for (int k = 0; k < 32; k++) {
            float a[8], b[8];
#pragma unroll
            for (int i = 0; i < 8; i++) a[i] = As[(ty * 8 + i) * 32 + k];
            *(float4*)&b[0] = *(float4*)&Bs[k * 128 + tx * 8];
            *(float4*)&b[4] = *(float4*)&Bs[k * 128 + tx * 8 + 4];
#pragma unroll
            for (int i = 0; i < 8; i++)
#pragma unroll
                for (int j = 0; j < 8; j++)
                    acc[i][j] = fmaf(a[i], b[j], acc[i][j]);
        }
        __syncthreads();
    }

    float bv[8];
#pragma unroll
    for (int j = 0; j < 8; j++) bv[j] = epi_bias ? epi_bias[tx * 8 + j] : 0.0f;

#pragma unroll
    for (int i = 0; i < 8; i++) {
        int grow = row0 + ty * 8 + i;
        if (grow < M) {
            float r[8];
#pragma unroll
            for (int j = 0; j < 8; j++) r[j] = acc[i][j] + bv[j];
            *(float4*)&outC[(size_t)grow * 128 + tx * 8]     = *(float4*)&r[0];
            *(float4*)&outC[(size_t)grow * 128 + tx * 8 + 4] = *(float4*)&r[4];
        }
    }
}

// ---------------- pull aggregation: one warp per target node -------------
// act[n] = t[n]*dinv[n]^2 + sum_{s in in(n)} dinv[s]*dinv[n]*t[s]
__global__ __launch_bounds__(256) void gather_kernel(int N) {
    const int warp = (int)((blockIdx.x * blockDim.x + threadIdx.x) >> 5);
    if (warp >= N) return;
    const int lane = threadIdx.x & 31;

    const int cnt = g_cursor[warp];
    const float dt = rsqrtf((float)cnt + 1.0f);

    float4 a0 = ((const float4*)(g_t + (size_t)warp * HID))[lane];
    const float s2 = dt * dt;
    a0.x *= s2; a0.y *= s2; a0.z *= s2; a0.w *= s2;
    float4 a1 = make_float4(0.f, 0.f, 0.f, 0.f);

    const int base = warp * CAP;
    for (int j0 = 0; j0 < cnt; j0 += 32) {
        const int m = min(32, cnt - j0);
        int   s_l = 0;
        float d_l = 0.f;
        if (lane < m) {
            s_l = g_srcs[base + j0 + lane];
            d_l = rsqrtf((float)g_cursor[s_l] + 1.0f) * dt;
        }
        int j = 0;
        for (; j + 2 <= m; j += 2) {
            int   sa = __shfl_sync(0xFFFFFFFFu, s_l, j);
            int   sb = __shfl_sync(0xFFFFFFFFu, s_l, j + 1);
            float na = __shfl_sync(0xFFFFFFFFu, d_l, j);
            float nb = __shfl_sync(0xFFFFFFFFu, d_l, j + 1);
            float4 va = ((const float4*)(g_t + (size_t)sa * HID))[lane];
            float4 vb = ((const float4*)(g_t + (size_t)sb * HID))[lane];
            a0.x = fmaf(na, va.x, a0.x); a0.y = fmaf(na, va.y, a0.y);
            a0.z = fmaf(na, va.z, a0.z); a0.w = fmaf(na, va.w, a0.w);
            a1.x = fmaf(nb, vb.x, a1.x); a1.y = fmaf(nb, vb.y, a1.y);
            a1.z = fmaf(nb, vb.z, a1.z); a1.w = fmaf(nb, vb.w, a1.w);
        }
        if (j < m) {
            int   sa = __shfl_sync(0xFFFFFFFFu, s_l, j);
            float na = __shfl_sync(0xFFFFFFFFu, d_l, j);
            float4 va = ((const float4*)(g_t + (size_t)sa * HID))[lane];
            a0.x = fmaf(na, va.x, a0.x); a0.y = fmaf(na, va.y, a0.y);
            a0.z = fmaf(na, va.z, a0.z); a0.w = fmaf(na, va.w, a0.w);
        }
    }
    a0.x += a1.x; a0.y += a1.y; a0.z += a1.z; a0.w += a1.w;
    ((float4*)(g_act + (size_t)warp * HID))[lane] = a0;
}

// ---------------- mean pool per graph (batch sorted), fused bias+relu ----
__device__ __forceinline__ int lower_bound_batch(const void* batch, int n, int val, int is64) {
    int lo = 0, hi = n;
    while (lo < hi) {
        int mid = (lo + hi) >> 1;
        long long b = is64 ? ((const long long*)batch)[mid]
                           : (long long)((const int*)batch)[mid];
        if (b < val) lo = mid + 1; else hi = mid;
    }
    return lo;
}

__global__ void pool_kernel(const void* __restrict__ batch,
                            const float* __restrict__ bias, int n) {
    const int g = blockIdx.x;
    const int tid = threadIdx.x;
    __shared__ int slo, shi;
    if (tid == 0) {
        int is64 = g_idx64;
        slo = lower_bound_batch(batch, n, g, is64);
        shi = lower_bound_batch(batch, n, g + 1, is64);
    }
    __syncthreads();
    const float b = bias[tid];
    float s0 = 0.f, s1 = 0.f, s2 = 0.f, s3 = 0.f;
    int lo = slo, hi = shi;
    int r = lo;
    for (; r + 4 <= hi; r += 4) {
        s0 += fmaxf(g_act[(size_t)(r + 0) * HID + tid] + b, 0.0f);
        s1 += fmaxf(g_act[(size_t)(r + 1) * HID + tid] + b, 0.0f);
        s2 += fmaxf(g_act[(size_t)(r + 2) * HID + tid] + b, 0.0f);
        s3 += fmaxf(g_act[(size_t)(r + 3) * HID + tid] + b, 0.0f);
    }
    for (; r < hi; r++)
        s0 += fmaxf(g_act[(size_t)r * HID + tid] + b, 0.0f);
    float sum = (s0 + s1) + (s2 + s3);
    float cnt = (float)(hi - lo);
    g_pooled[g * HID + tid] = sum / fmaxf(cnt, 1.0f);
}

// ---------------- heads --------------------------------------------------
__global__ void heads_kernel(
    const float* __restrict__ Wd, const float* __restrict__ bd,
    const float* __restrict__ Ws, const float* __restrict__ bsn,
    const float* __restrict__ Wr, const float* __restrict__ br,
    float* __restrict__ out)
{
    const int g = blockIdx.x;
    const int head = blockIdx.y;
    const int j = threadIdx.x;
    __shared__ float p[HID];
    p[j] = g_pooled[g * HID + j];
    __syncthreads();

    const float* W = (head == 0) ? Wd : (head == 1) ? Ws : Wr;
    const float* b = (head == 0) ? bd : (head == 1) ? bsn : br;
    float s = b[j];
#pragma unroll 8
    for (int k = 0; k < HID; k++)
        s = fmaf(p[k], W[k * HID + j], s);
    out[(size_t)head * NGRAPH * HID + g * HID + j] = s;
}

// ---------------- launch --------------------------------------------------
extern "C" void kernel_launch(void* const* d_in, const int* in_sizes, int n_in,
                              void* d_out, int out_size)
{
    const float* x      = (const float*)d_in[0];
    const void*  eidx   = d_in[1];
    const void*  batch  = d_in[2];
    const float* W_in   = (const float*)d_in[3];
    const float* b_in   = (const float*)d_in[4];
    const float* conv_W = (const float*)d_in[5];
    const float* conv_b = (const float*)d_in[6];
    const float* W_def  = (const float*)d_in[7];
    const float* b_def  = (const float*)d_in[8];
    const float* W_syn  = (const float*)d_in[9];
    const float* b_syn  = (const float*)d_in[10];
    const float* W_rel  = (const float*)d_in[11];
    const float* b_rel  = (const float*)d_in[12];
    float* out = (float*)d_out;

    const int N = in_sizes[0] / HID;       // 50000
    const int E = in_sizes[1] / 2;         // 640000

    void *pt, *pa;
    cudaGetSymbolAddress(&pt, g_t);
    cudaGetSymbolAddress(&pa, g_act);
    float* t_buf   = (float*)pt;
    float* act_buf = (float*)pa;

    const int T = 256;
    const int GB = (N + 127) / 128;

    // 0. index dtype detection
    detect_dtype_kernel<<<1, 32>>>((const int*)eidx);

    // 1. adjacency build (replaces per-layer feature atomics)
    zero_kernel<<<(N + T - 1) / T, T>>>(N);
    fill_kernel<<<(E + T - 1) / T, T>>>(eidx, E);

    // 2. input layer: act = x @ W_in + b_in (pre-activation)
    gemm_kernel<false><<<GB, 256>>>(x, W_in, nullptr, b_in, act_buf, N);

    // 3. GCN layers: GEMM (relu+bias fused in prologue) then pull-gather
    for (int l = 0; l < NLAYERS; l++) {
        const float* pro_b = (l == 0) ? nullptr : conv_b + (size_t)(l - 1) * HID;
        gemm_kernel<true><<<GB, 256>>>(
            act_buf, conv_W + (size_t)l * HID * HID, pro_b, nullptr, t_buf, N);
        gather_kernel<<<(N * 32 + T - 1) / T, T>>>(N);
    }

    // 4. global mean pool with fused final bias+relu
    pool_kernel<<<NGRAPH, HID>>>(batch, conv_b + (size_t)(NLAYERS - 1) * HID, N);

    // 5. output heads
    heads_kernel<<<dim3(NGRAPH, 3), HID>>>(W_def, b_def, W_syn, b_syn,
                                           W_rel, b_rel, out);
}

// round 4
// speedup vs baseline: 1.4326x; 1.0127x over previous
#include <cuda_runtime.h>
#include <cstdint>

#define NN      50000
#define NGRAPH  64
#define HID     128
#define NLAYERS 4
#define CAP     192     // per-node in-edge capacity (max in-degree ~45 expected)

#define SA 132          // A tile row stride (floats): banks (4g+t) conflict-free
#define SW 136          // W tile row stride (floats): banks (8t+g) conflict-free
#define SMEM_BYTES ((128 * SA + 128 * SW) * 4)   // 137216

// ---------------- scratch (no allocations allowed) ----------------
__device__ float g_t[NN * HID];       // h @ W  (message source)
__device__ float g_act[NN * HID];     // activation / aggregation buffer
__device__ int   g_srcs[NN * CAP];    // bucketed in-edge source lists
__device__ int   g_cursor[NN];        // in-degree (w/o self loop)
__device__ float g_pooled[NGRAPH * HID];
__device__ int   g_idx64;             // 1 if index buffers are int64

// ---------------- dtype detection (warp-parallel) ----------------
__global__ void detect_dtype_kernel(const int* __restrict__ e) {
    int lane = threadIdx.x;
    int nz = 0;
    if (e[1 + 2 * lane] != 0) nz = 1;
    if (e[1 + 2 * (lane + 32)] != 0) nz = 1;
    unsigned m = __ballot_sync(0xFFFFFFFFu, nz);
    if (lane == 0) g_idx64 = (m == 0u) ? 1 : 0;
}

// ---------------- adjacency build --------------------------------
__global__ void zero_kernel(int n) {
    int i = blockIdx.x * blockDim.x + threadIdx.x;
    if (i < n) g_cursor[i] = 0;
}

__global__ void fill_kernel(const void* __restrict__ eidx, int E) {
    const int is64 = g_idx64;
    int i = blockIdx.x * blockDim.x + threadIdx.x;
    if (i < E) {
        int s, t;
        if (is64) {
            s = (int)((const long long*)eidx)[i];
            t = (int)((const long long*)eidx)[(long long)E + i];
        } else {
            s = ((const int*)eidx)[i];
            t = ((const int*)eidx)[E + i];
        }
        int p = atomicAdd(&g_cursor[t], 1);
        if (p < CAP) g_srcs[t * CAP + p] = s;
    }
}

// ---------------- tf32 helpers -----------------------------------
__device__ __forceinline__ uint32_t f2tf32(float f) {
    uint32_t r;
    asm("cvt.rna.tf32.f32 %0, %1;" : "=r"(r) : "f"(f));
    return r;
}
__device__ __forceinline__ void split_tf32(float f, uint32_t& hi, uint32_t& lo) {
    hi = f2tf32(f);
    lo = f2tf32(f - __uint_as_float(hi));
}
__device__ __forceinline__ void mma_tf32(
    float& c0, float& c1, float& c2, float& c3,
    uint32_t a0, uint32_t a1, uint32_t a2, uint32_t a3,
    uint32_t b0, uint32_t b1)
{
    asm volatile(
        "mma.sync.aligned.m16n8k8.row.col.f32.tf32.tf32.f32 "
        "{%0,%1,%2,%3}, {%4,%5,%6,%7}, {%8,%9}, {%0,%1,%2,%3};"
        : "+f"(c0), "+f"(c1), "+f"(c2), "+f"(c3)
        : "r"(a0), "r"(a1), "r"(a2), "r"(a3), "r"(b0), "r"(b1));
}

// ---------------- 3xTF32 tensor-core GEMM ------------------------
// C[M,128] = op(A)[M,128] @ W[128,128] (+ epi_bias)
//   PRO: op(a)[r][c] = relu(a[r][c] + pro_bias[c])   (pro_bias may be null)
// BM=128, full N=128, full K=128 (no k-loop). 256 threads = 8 warps (4M x 2N),
// warp tile 32(M) x 64(N). A=hi+lo, B=hi+lo; 3 MMAs per product term.
template<bool PRO>
__global__ __launch_bounds__(256) void gemm_kernel(
    const float* A, const float* __restrict__ W,
    const float* __restrict__ pro_bias, const float* __restrict__ epi_bias,
    float* outC, int M)
{
    extern __shared__ float smem[];
    float* As = smem;                 // [128][SA]
    float* Ws = smem + 128 * SA;      // [128][SW]

    const int tid = threadIdx.x;
    const int row0 = blockIdx.x * 128;

    // ---- load A tile (with optional fused bias+relu) ----
#pragma unroll
    for (int l = 0; l < 16; l++) {
        int f = tid + l * 256;            // 0..4095 float4 slots
        int r = f >> 5;                   // row (32 float4 per row)
        int c4 = f & 31;                  // float4 col
        int grow = row0 + r;
        float4 v = make_float4(0.f, 0.f, 0.f, 0.f);
        if (grow < M) {
            v = *(const float4*)&A[(size_t)grow * 128 + c4 * 4];
            if (PRO) {
                float4 b = make_float4(0.f, 0.f, 0.f, 0.f);
                if (pro_bias) b = ((const float4*)pro_bias)[c4];
                v.x = fmaxf(v.x + b.x, 0.0f);
                v.y = fmaxf(v.y + b.y, 0.0f);
                v.z = fmaxf(v.z + b.z, 0.0f);
                v.w = fmaxf(v.w + b.w, 0.0f);
            }
        }
        *(float4*)&As[r * SA + c4 * 4] = v;
    }
    // ---- load W tile ----
#pragma unroll
    for (int l = 0; l < 16; l++) {
        int f = tid + l * 256;
        int r = f >> 5;
        int c4 = f & 31;
        *(float4*)&Ws[r * SW + c4 * 4] = *(const float4*)&W[(size_t)r * 128 + c4 * 4];
    }
    __syncthreads();

    const int warp = tid >> 5;
    const int lane = tid & 31;
    const int g = lane >> 2;          // group id 0..7
    const int t = lane & 3;           // thread-in-group 0..3
    const int wm = (warp >> 1) * 32;  // warp M offset
    const int wn = (warp & 1) * 64;   // warp N offset

    float C[2][8][4];
#pragma unroll
    for (int i = 0; i < 2; i++)
#pragma unroll
        for (int j = 0; j < 8; j++)
#pragma unroll
            for (int q = 0; q < 4; q++) C[i][j][q] = 0.0f;

#pragma unroll
    for (int k8 = 0; k8 < 16; k8++) {
        const int k0 = k8 * 8;
        // A fragments (m16k8 each), 2 per warp tile
        uint32_t Ah[2][4], Al[2][4];
#pragma unroll
        for (int i = 0; i < 2; i++) {
            const int rb = wm + i * 16;
            float a0 = As[(rb + g) * SA + k0 + t];
            float a1 = As[(rb + 8 + g) * SA + k0 + t];
            float a2 = As[(rb + g) * SA + k0 + t + 4];
            float a3 = As[(rb + 8 + g) * SA + k0 + t + 4];
            split_tf32(a0, Ah[i][0], Al[i][0]);
            split_tf32(a1, Ah[i][1], Al[i][1]);
            split_tf32(a2, Ah[i][2], Al[i][2]);
            split_tf32(a3, Ah[i][3], Al[i][3]);
        }
#pragma unroll
        for (int j = 0; j < 8; j++) {
            const int n0 = wn + j * 8;
            float b0f = Ws[(k0 + t) * SW + n0 + g];
            float b1f = Ws[(k0 + t + 4) * SW + n0 + g];
            uint32_t bh0, bl0, bh1, bl1;
            split_tf32(b0f, bh0, bl0);
            split_tf32(b1f, bh1, bl1);
#pragma unroll
            for (int i = 0; i < 2; i++) {
                mma_tf32(C[i][j][0], C[i][j][1], C[i][j][2], C[i][j][3],
                         Ah[i][0], Ah[i][1], Ah[i][2], Ah[i][3], bh0, bh1);
                mma_tf32(C[i][j][0], C[i][j][1], C[i][j][2], C[i][j][3],
                         Ah[i][0], Ah[i][1], Ah[i][2], Ah[i][3], bl0, bl1);
                mma_tf32(C[i][j][0], C[i][j][1], C[i][j][2], C[i][j][3],
                         Al[i][0], Al[i][1], Al[i][2], Al[i][3], bh0, bh1);
            }
        }
    }

    // ---- epilogue ----
#pragma unroll
    for (int i = 0; i < 2; i++) {
#pragma unroll
        for (int j = 0; j < 8; j++) {
            const int col = wn + j * 8 + 2 * t;
            float be0 = 0.f, be1 = 0.f;
            if (epi_bias) { be0 = epi_bias[col]; be1 = epi_bias[col + 1]; }
            const int r0 = row0 + wm + i * 16 + g;
            const int r1 = r0 + 8;
            if (r0 < M) {
                float2 v = make_float2(C[i][j][0] + be0, C[i][j][1] + be1);
                *(float2*)&outC[(size_t)r0 * 128 + col] = v;
            }
            if (r1 < M) {
                float2 v = make_float2(C[i][j][2] + be0, C[i][j][3] + be1);
                *(float2*)&outC[(size_t)r1 * 128 + col] = v;
            }
        }
    }
}

// ---------------- pull aggregation: one warp per target node -------------
// act[n] = t[n]*dinv[n]^2 + sum_{s in in(n)} dinv[s]*dinv[n]*t[s]
__global__ __launch_bounds__(256) void gather_kernel(int N) {
    const int warp = (int)((blockIdx.x * blockDim.x + threadIdx.x) >> 5);
    if (warp >= N) return;
    const int lane = threadIdx.x & 31;

    const int cnt = g_cursor[warp];
    const float dt = rsqrtf((float)cnt + 1.0f);

    float4 a0 = ((const float4*)(g_t + (size_t)warp * HID))[lane];
    const float s2 = dt * dt;
    a0.x *= s2; a0.y *= s2; a0.z *= s2; a0.w *= s2;
    float4 a1 = make_float4(0.f, 0.f, 0.f, 0.f);

    const int base = warp * CAP;
    for (int j0 = 0; j0 < cnt; j0 += 32) {
        const int m = min(32, cnt - j0);
        int   s_l = 0;
        float d_l = 0.f;
        if (lane < m) {
            s_l = g_srcs[base + j0 + lane];
            d_l = rsqrtf((float)g_cursor[s_l] + 1.0f) * dt;
        }
        int j = 0;
        for (; j + 2 <= m; j += 2) {
            int   sa = __shfl_sync(0xFFFFFFFFu, s_l, j);
            int   sb = __shfl_sync(0xFFFFFFFFu, s_l, j + 1);
            float na = __shfl_sync(0xFFFFFFFFu, d_l, j);
            float nb = __shfl_sync(0xFFFFFFFFu, d_l, j + 1);
            float4 va = ((const float4*)(g_t + (size_t)sa * HID))[lane];
            float4 vb = ((const float4*)(g_t + (size_t)sb * HID))[lane];
            a0.x = fmaf(na, va.x, a0.x); a0.y = fmaf(na, va.y, a0.y);
            a0.z = fmaf(na, va.z, a0.z); a0.w = fmaf(na, va.w, a0.w);
            a1.x = fmaf(nb, vb.x, a1.x); a1.y = fmaf(nb, vb.y, a1.y);
            a1.z = fmaf(nb, vb.z, a1.z); a1.w = fmaf(nb, vb.w, a1.w);
        }
        if (j < m) {
            int   sa = __shfl_sync(0xFFFFFFFFu, s_l, j);
            float na = __shfl_sync(0xFFFFFFFFu, d_l, j);
            float4 va = ((const float4*)(g_t + (size_t)sa * HID))[lane];
            a0.x = fmaf(na, va.x, a0.x); a0.y = fmaf(na, va.y, a0.y);
            a0.z = fmaf(na, va.z, a0.z); a0.w = fmaf(na, va.w, a0.w);
        }
    }
    a0.x += a1.x; a0.y += a1.y; a0.z += a1.z; a0.w += a1.w;
    ((float4*)(g_act + (size_t)warp * HID))[lane] = a0;
}

// ---------------- mean pool per graph (batch sorted), fused bias+relu ----
__device__ __forceinline__ int lower_bound_batch(const void* batch, int n, int val, int is64) {
    int lo = 0, hi = n;
    while (lo < hi) {
        int mid = (lo + hi) >> 1;
        long long b = is64 ? ((const long long*)batch)[mid]
                           : (long long)((const int*)batch)[mid];
        if (b < val) lo = mid + 1; else hi = mid;
    }
    return lo;
}

__global__ void pool_kernel(const void* __restrict__ batch,
                            const float* __restrict__ bias, int n) {
    const int g = blockIdx.x;
    const int tid = threadIdx.x;
    __shared__ int slo, shi;
    if (tid == 0) {
        int is64 = g_idx64;
        slo = lower_bound_batch(batch, n, g, is64);
        shi = lower_bound_batch(batch, n, g + 1, is64);
    }
    __syncthreads();
    const float b = bias[tid];
    float s0 = 0.f, s1 = 0.f, s2 = 0.f, s3 = 0.f;
    int lo = slo, hi = shi;
    int r = lo;
    for (; r + 4 <= hi; r += 4) {
        s0 += fmaxf(g_act[(size_t)(r + 0) * HID + tid] + b, 0.0f);
        s1 += fmaxf(g_act[(size_t)(r + 1) * HID + tid] + b, 0.0f);
        s2 += fmaxf(g_act[(size_t)(r + 2) * HID + tid] + b, 0.0f);
        s3 += fmaxf(g_act[(size_t)(r + 3) * HID + tid] + b, 0.0f);
    }
    for (; r < hi; r++)
        s0 += fmaxf(g_act[(size_t)r * HID + tid] + b, 0.0f);
    float sum = (s0 + s1) + (s2 + s3);
    float cnt = (float)(hi - lo);
    g_pooled[g * HID + tid] = sum / fmaxf(cnt, 1.0f);
}

// ---------------- heads --------------------------------------------------
__global__ void heads_kernel(
    const float* __restrict__ Wd, const float* __restrict__ bd,
    const float* __restrict__ Ws, const float* __restrict__ bsn,
    const float* __restrict__ Wr, const float* __restrict__ br,
    float* __restrict__ out)
{
    const int g = blockIdx.x;
    const int head = blockIdx.y;
    const int j = threadIdx.x;
    __shared__ float p[HID];
    p[j] = g_pooled[g * HID + j];
    __syncthreads();

    const float* W = (head == 0) ? Wd : (head == 1) ? Ws : Wr;
    const float* b = (head == 0) ? bd : (head == 1) ? bsn : br;
    float s = b[j];
#pragma unroll 8
    for (int k = 0; k < HID; k++)
        s = fmaf(p[k], W[k * HID + j], s);
    out[(size_t)head * NGRAPH * HID + g * HID + j] = s;
}

// ---------------- launch --------------------------------------------------
extern "C" void kernel_launch(void* const* d_in, const int* in_sizes, int n_in,
                              void* d_out, int out_size)
{
    const float* x      = (const float*)d_in[0];
    const void*  eidx   = d_in[1];
    const void*  batch  = d_in[2];
    const float* W_in   = (const float*)d_in[3];
    const float* b_in   = (const float*)d_in[4];
    const float* conv_W = (const float*)d_in[5];
    const float* conv_b = (const float*)d_in[6];
    const float* W_def  = (const float*)d_in[7];
    const float* b_def  = (const float*)d_in[8];
    const float* W_syn  = (const float*)d_in[9];
    const float* b_syn  = (const float*)d_in[10];
    const float* W_rel  = (const float*)d_in[11];
    const float* b_rel  = (const float*)d_in[12];
    float* out = (float*)d_out;

    const int N = in_sizes[0] / HID;       // 50000
    const int E = in_sizes[1] / 2;         // 640000

    void *pt, *pa;
    cudaGetSymbolAddress(&pt, g_t);
    cudaGetSymbolAddress(&pa, g_act);
    float* t_buf   = (float*)pt;
    float* act_buf = (float*)pa;

    // allow 137KB dynamic smem on the GEMM (host-side attribute, idempotent)
    static int smem_set = 0;
    if (!smem_set) {
        cudaFuncSetAttribute(gemm_kernel<false>,
                             cudaFuncAttributeMaxDynamicSharedMemorySize, SMEM_BYTES);
        cudaFuncSetAttribute(gemm_kernel<true>,
                             cudaFuncAttributeMaxDynamicSharedMemorySize, SMEM_BYTES);
        smem_set = 1;
    }

    const int T = 256;
    const int GB = (N + 127) / 128;

    // 0. index dtype detection
    detect_dtype_kernel<<<1, 32>>>((const int*)eidx);

    // 1. adjacency build
    zero_kernel<<<(N + T - 1) / T, T>>>(N);
    fill_kernel<<<(E + T - 1) / T, T>>>(eidx, E);

    // 2. input layer: act = x @ W_in + b_in (pre-activation)
    gemm_kernel<false><<<GB, 256, SMEM_BYTES>>>(x, W_in, nullptr, b_in, act_buf, N);

    // 3. GCN layers: GEMM (relu+bias fused in prologue) then pull-gather
    for (int l = 0; l < NLAYERS; l++) {
        const float* pro_b = (l == 0) ? nullptr : conv_b + (size_t)(l - 1) * HID;
        gemm_kernel<true><<<GB, 256, SMEM_BYTES>>>(
            act_buf, conv_W + (size_t)l * HID * HID, pro_b, nullptr, t_buf, N);
        gather_kernel<<<(N * 32 + T - 1) / T, T>>>(N);
    }

    // 4. global mean pool with fused final bias+relu
    pool_kernel<<<NGRAPH, HID>>>(batch, conv_b + (size_t)(NLAYERS - 1) * HID, N);

    // 5. output heads
    heads_kernel<<<dim3(NGRAPH, 3), HID>>>(W_def, b_def, W_syn, b_syn,
                                           W_rel, b_rel, out);
}